// round 10
// baseline (speedup 1.0000x reference)
#include <cuda_runtime.h>
#include <cstdint>

#define BT 131072   // B*T = 256*512
#define TT 512

typedef unsigned long long ull;

// ---------------- scratch (device globals; no runtime allocation) ----------
__device__ float g_bufG[67108864];  // [BT,512]  G1 / G2 / Gd2 (reused)
__device__ float g_h1[16777216];    // [BT,128]
__device__ float g_d1[8388608];     // [BT,64]
__device__ float g_z[16384];        // [256,64]
__device__ float g_gd1[65536];      // [256,256]

// ---------------- packed f32x2 helpers --------------------------------------
__device__ __forceinline__ ull dup2(float x) {
    ull r; asm("mov.b64 %0, {%1, %1};" : "=l"(r) : "f"(x)); return r;
}
__device__ __forceinline__ ull pack2(float lo, float hi) {
    ull r; asm("mov.b64 %0, {%1, %2};" : "=l"(r) : "f"(lo), "f"(hi)); return r;
}
__device__ __forceinline__ float2 unpack2(ull v) {
    float2 f; asm("mov.b64 {%0, %1}, %2;" : "=f"(f.x), "=f"(f.y) : "l"(v)); return f;
}
__device__ __forceinline__ void fma2(ull& acc, ull a, ull b) {
    asm("fma.rn.f32x2 %0, %1, %2, %0;" : "+l"(acc) : "l"(a), "l"(b));
}
__device__ __forceinline__ ull add2(ull a, ull b) {
    ull d; asm("add.rn.f32x2 %0, %1, %2;" : "=l"(d) : "l"(a), "l"(b)); return d;
}

// fast sigmoid: 1/(1 + 2^(-x*log2e)) via ex2.approx + rcp.approx (~1e-6 rel)
__device__ __forceinline__ float fsig(float x) {
    float r;
    asm("{\n\t.reg .f32 t;\n\t"
        "mul.f32 t, %1, 0fBFB8AA3B;\n\t"
        "ex2.approx.f32 t, t;\n\t"
        "add.f32 t, t, 0f3F800000;\n\t"
        "rcp.approx.f32 %0, t;\n\t}"
        : "=f"(r) : "f"(x));
    return r;
}

// ---------------- misc helpers ----------------------------------------------
__device__ __forceinline__ void cp_async16(void* smem_dst, const void* gmem_src) {
    uint32_t s = (uint32_t)__cvta_generic_to_shared(smem_dst);
    asm volatile("cp.async.cg.shared.global [%0], [%1], 16;\n" :: "r"(s), "l"(gmem_src));
}
__device__ __forceinline__ void cp_async_commit() { asm volatile("cp.async.commit_group;\n"); }
__device__ __forceinline__ void cp_async_wait6()  { asm volatile("cp.async.wait_group 6;\n"); }
__device__ __forceinline__ void cp_async_wait0()  { asm volatile("cp.async.wait_group 0;\n"); }

__device__ __forceinline__ void cluster_sync_() {
    asm volatile("barrier.cluster.arrive.aligned;\n" ::: "memory");
    asm volatile("barrier.cluster.wait.aligned;\n" ::: "memory");
}
__device__ __forceinline__ void st_remote_f32(float* local_ptr, uint32_t peer, float v) {
    uint32_t la = (uint32_t)__cvta_generic_to_shared(local_ptr);
    uint32_t ra;
    asm("mapa.shared::cluster.u32 %0, %1, %2;\n" : "=r"(ra) : "r"(la), "r"(peer));
    asm volatile("st.shared::cluster.f32 [%0], %1;\n" :: "r"(ra), "f"(v) : "memory");
}
__device__ __forceinline__ void mbar_arrive_remote(uint32_t local_mbar, uint32_t peer) {
    uint32_t ra;
    asm("mapa.shared::cluster.u32 %0, %1, %2;\n" : "=r"(ra) : "r"(local_mbar), "r"(peer));
    asm volatile("mbarrier.arrive.release.cluster.shared::cluster.b64 _, [%0];\n"
                 :: "r"(ra) : "memory");
}
__device__ __forceinline__ void mbar_wait(uint32_t mbar, uint32_t parity) {
    asm volatile(
        "{\n\t.reg .pred P;\n"
        "WAITL_%=:\n\t"
        "mbarrier.try_wait.parity.acquire.cluster.shared::cta.b64 P, [%0], %1, 0x989680;\n\t"
        "@!P bra WAITL_%=;\n"
        "}" :: "r"(mbar), "r"(parity) : "memory");
}

// ---------------- bulk GEMM: C[M,N] = A[M,K] @ W[K,N] + bias ----------------
// 128x128 tile, BK=16, 256 threads, f32x2 accumulation.
// A tile stored PRE-DUPLICATED in smem as (a,a) ull pairs: consumers do
// 4 LDS.128 + 32 fma2 per k (no dup movs in the hot loop).
// Dynamic smem: As2 2*16*128 ull (32KB) + Bs 2*16*128 f32 (16KB) = 48KB.
__global__ void __launch_bounds__(256)
gemm_f32x2_kernel(const float* __restrict__ A,
                  const float* __restrict__ W,
                  const float* __restrict__ bias,
                  float* __restrict__ C,
                  int M, int N, int K) {
    extern __shared__ __align__(16) float smf[];
    ull* As2 = (ull*)smf;                 // [2][16][128] ull
    float* Bsf = smf + 8192;              // [2][16][128] f32
#define AS2_(b, k, r) As2[(b) * 2048 + (k) * 128 + (r)]
#define BS_(b, k, n)  Bsf[(b) * 2048 + (k) * 128 + (n)]

    const int tid = threadIdx.x;
    const int m0 = blockIdx.x * 128, n0 = blockIdx.y * 128;
    const int tx = tid & 15, ty = tid >> 4;

    const int am = tid >> 1, ak = (tid & 1) * 8;

    ull acc[8][4];
#pragma unroll
    for (int i = 0; i < 8; i++)
#pragma unroll
        for (int j = 0; j < 4; j++) acc[i][j] = 0ull;

    const int nk = K / 16;

    {
        const float* ap = A + (size_t)(m0 + am) * K + ak;
        float4 va = *(const float4*)ap;
        float4 vb = *(const float4*)(ap + 4);
#pragma unroll
        for (int q = 0; q < 2; q++) {
            int idx = tid * 2 + q;
            int br = idx >> 5, bc = (idx & 31) * 4;
            cp_async16(&BS_(0, br, bc), W + (size_t)br * N + n0 + bc);
        }
        cp_async_commit();
        AS2_(0, ak + 0, am) = dup2(va.x); AS2_(0, ak + 1, am) = dup2(va.y);
        AS2_(0, ak + 2, am) = dup2(va.z); AS2_(0, ak + 3, am) = dup2(va.w);
        AS2_(0, ak + 4, am) = dup2(vb.x); AS2_(0, ak + 5, am) = dup2(vb.y);
        AS2_(0, ak + 6, am) = dup2(vb.z); AS2_(0, ak + 7, am) = dup2(vb.w);
        cp_async_wait0();
        __syncthreads();
    }

    for (int kt = 0; kt < nk; kt++) {
        const int p = kt & 1;
        const bool more = (kt + 1) < nk;
        float4 va, vb;
        if (more) {
            const float* ap = A + (size_t)(m0 + am) * K + (kt + 1) * 16 + ak;
            va = *(const float4*)ap;
            vb = *(const float4*)(ap + 4);
#pragma unroll
            for (int q = 0; q < 2; q++) {
                int idx = tid * 2 + q;
                int br = idx >> 5, bc = (idx & 31) * 4;
                cp_async16(&BS_(p ^ 1, br, bc), W + (size_t)((kt + 1) * 16 + br) * N + n0 + bc);
            }
        }
        cp_async_commit();

#pragma unroll
        for (int k = 0; k < 16; k++) {
            ulonglong2 aA = *(const ulonglong2*)&AS2_(p, k, ty * 4);
            ulonglong2 aB = *(const ulonglong2*)&AS2_(p, k, ty * 4 + 2);
            ulonglong2 aC = *(const ulonglong2*)&AS2_(p, k, 64 + ty * 4);
            ulonglong2 aD = *(const ulonglong2*)&AS2_(p, k, 64 + ty * 4 + 2);
            ulonglong2 b0v = *(const ulonglong2*)&BS_(p, k, tx * 4);
            ulonglong2 b1v = *(const ulonglong2*)&BS_(p, k, 64 + tx * 4);
            ull av[8] = {aA.x, aA.y, aB.x, aB.y, aC.x, aC.y, aD.x, aD.y};
#pragma unroll
            for (int i = 0; i < 8; i++) {
                fma2(acc[i][0], av[i], b0v.x);
                fma2(acc[i][1], av[i], b0v.y);
                fma2(acc[i][2], av[i], b1v.x);
                fma2(acc[i][3], av[i], b1v.y);
            }
        }

        if (more) {
            AS2_(p ^ 1, ak + 0, am) = dup2(va.x); AS2_(p ^ 1, ak + 1, am) = dup2(va.y);
            AS2_(p ^ 1, ak + 2, am) = dup2(va.z); AS2_(p ^ 1, ak + 3, am) = dup2(va.w);
            AS2_(p ^ 1, ak + 4, am) = dup2(vb.x); AS2_(p ^ 1, ak + 5, am) = dup2(vb.y);
            AS2_(p ^ 1, ak + 6, am) = dup2(vb.z); AS2_(p ^ 1, ak + 7, am) = dup2(vb.w);
        }
        cp_async_wait0();
        __syncthreads();
    }

    ull bz[4];
    bz[0] = *(const ull*)&bias[n0 + tx * 4];
    bz[1] = *(const ull*)&bias[n0 + tx * 4 + 2];
    bz[2] = *(const ull*)&bias[n0 + 64 + tx * 4];
    bz[3] = *(const ull*)&bias[n0 + 64 + tx * 4 + 2];
#pragma unroll
    for (int i = 0; i < 8; i++) {
        int row = m0 + ((i < 4) ? (ty * 4 + i) : (64 + ty * 4 + i - 4));
        ulonglong2 o0;
        o0.x = add2(acc[i][0], bz[0]);
        o0.y = add2(acc[i][1], bz[1]);
        *(ulonglong2*)&C[(size_t)row * N + n0 + tx * 4] = o0;
        ulonglong2 o1;
        o1.x = add2(acc[i][2], bz[2]);
        o1.y = add2(acc[i][3], bz[3]);
        *(ulonglong2*)&C[(size_t)row * N + n0 + 64 + tx * 4] = o1;
    }
#undef AS2_
#undef BS_
}

// ---------------- LSTM recurrence, H=64 (R4 version; measured ~265us) -------
__global__ void __launch_bounds__(256)
lstm64_kernel(const float* __restrict__ gproj, // [BT,256] or [256,256] if constProj
              const float* __restrict__ Wr,    // [64,256]
              float* __restrict__ hseq,        // [BT,64] or null
              float* __restrict__ hlast,       // [256,64] or null
              int constProj) {
    __shared__ __align__(16) float h_s[2][2][64];
    __shared__ __align__(16) float gbuf[8][2][256];   // 16KB

    const int tid = threadIdx.x;
    const int b0 = blockIdx.x * 2;
    const int w = tid >> 5, lane = tid & 31;
    const int r = w >> 2;                    // row 0/1
    const int j = (w & 3) * 16 + (lane & 15);
    const int kh = lane >> 4;                // k half: k in [kh*32, kh*32+32)

    ull w2[64];
#pragma unroll
    for (int g = 0; g < 4; g++)
#pragma unroll
        for (int kp = 0; kp < 16; kp++) {
            int k = kh * 32 + 2 * kp;
            w2[g * 16 + kp] = pack2(Wr[k * 256 + g * 64 + j],
                                    Wr[(k + 1) * 256 + g * 64 + j]);
        }

    if (tid < 128) h_s[0][tid >> 6][tid & 63] = 0.f;

    const int pr = tid >> 6, c4 = (tid & 63) * 4;
    float gc[4] = {0.f, 0.f, 0.f, 0.f};
    if (constProj) {
#pragma unroll
        for (int g = 0; g < 4; g++)
            gc[g] = gproj[(size_t)(b0 + r) * 256 + g * 64 + j];
    } else {
        for (int s = 0; s < 7; s++) {
            if (tid < 128)
                cp_async16(&gbuf[s][pr][c4], gproj + ((size_t)(b0 + pr) * TT + s) * 256 + c4);
            cp_async_commit();
        }
        cp_async_wait6();
    }
    __syncthreads();

    float c = 0.f;
    float hcur = 0.f;
    int p = 0;

    for (int t = 0; t < TT; t++) {
        const int st = t & 7;
        if (!constProj) {
            if (tid < 128 && t + 7 < TT)
                cp_async16(&gbuf[(t + 7) & 7][pr][c4],
                           gproj + ((size_t)(b0 + pr) * TT + t + 7) * 256 + c4);
            cp_async_commit();
        }

        ull hv[16];
        const float* hp = &h_s[p][r][kh * 32];
#pragma unroll
        for (int q = 0; q < 8; q++) {
            ulonglong2 v = *(const ulonglong2*)(hp + q * 4);
            hv[q * 2] = v.x; hv[q * 2 + 1] = v.y;
        }

        ull ae[4] = {0ull, 0ull, 0ull, 0ull};
        ull ao[4] = {0ull, 0ull, 0ull, 0ull};
#pragma unroll
        for (int kp = 0; kp < 16; kp += 2) {
#pragma unroll
            for (int g = 0; g < 4; g++) {
                fma2(ae[g], w2[g * 16 + kp], hv[kp]);
                fma2(ao[g], w2[g * 16 + kp + 1], hv[kp + 1]);
            }
        }
        float s[4];
#pragma unroll
        for (int g = 0; g < 4; g++) {
            float2 f = unpack2(add2(ae[g], ao[g]));
            s[g] = f.x + f.y;
            s[g] += __shfl_xor_sync(0xffffffffu, s[g], 16);
        }

        float zi, zf, zg, zo;
        if (constProj) {
            zi = s[0] + gc[0]; zf = s[1] + gc[1]; zg = s[2] + gc[2]; zo = s[3] + gc[3];
        } else {
            zi = s[0] + gbuf[st][r][j];
            zf = s[1] + gbuf[st][r][64 + j];
            zg = s[2] + gbuf[st][r][128 + j];
            zo = s[3] + gbuf[st][r][192 + j];
        }
        c = fsig(zf) * c + fsig(zi) * fmaxf(zg, 0.f);
        hcur = fsig(zo) * fmaxf(c, 0.f);
        if (kh == 0) h_s[p ^ 1][r][j] = hcur;
        else if (hseq) hseq[((size_t)(b0 + r) * TT + t) * 64 + j] = hcur;

        if (!constProj) cp_async_wait6();
        __syncthreads();
        p ^= 1;
    }
    if (hlast && kh == 0)
        hlast[(size_t)(b0 + r) * 64 + j] = hcur;
}

// ---------------- LSTM recurrence, H=128 (R3 256-thr core + fused out) ------
// 2-CTA cluster, 64 clusters, 4 batch rows per CTA. Threads 0-255: exact R3
// structure (thread = gate-col, 4 rows, z_s roundtrip). Optional extra warps
// (launch 384 threads when Wout != null): threads 256-383 are barrier-only in
// phase 1 and compute the fused out(t-1) = h(t-1) @ Wout + bout in phase 2.
// Dynamic smem (floats): h_s 1024 | z_s 1024 | gbuf 8192 | wo2 4096 | bo 32 | mbar 2
__global__ void __launch_bounds__(384) __cluster_dims__(2, 1, 1)
lstm128_kernel(const float* __restrict__ gproj, // [BT,512]
               const float* __restrict__ Wr,    // [128,512]
               float* __restrict__ hseq,        // [BT,128] or null
               const float* __restrict__ Wout,  // [128,64] or null (fused out)
               const float* __restrict__ bout,  // [64]
               float* __restrict__ outp) {      // [BT,64]
    extern __shared__ __align__(16) float sm[];
    float (*h_s)[4][128]  = (float (*)[4][128])sm;           // [2][4][128]
    float (*z_s)[256]     = (float (*)[256])(sm + 1024);     // [4][256]
    float (*gbuf)[4][256] = (float (*)[4][256])(sm + 2048);  // [8][4][256]
    ull (*wo2)[32]        = (ull (*)[32])(sm + 10240);       // [64][32]
    float* bo_s           = sm + 14336;                      // [32]
    ull* mbar_p           = (ull*)(sm + 14368);

    const int tid = threadIdx.x;
    const int nthr = blockDim.x;
    uint32_t q;
    asm("mov.u32 %0, %%cluster_ctarank;" : "=r"(q));
    const uint32_t peer = q ^ 1u;
    const int b0 = (blockIdx.x >> 1) * 4;
    const int gcol = ((tid >> 6) & 3) * 128 + (int)q * 64 + (tid & 63);

    ull w2[64];
    if (tid < 256) {
#pragma unroll
        for (int kp = 0; kp < 64; kp++)
            w2[kp] = pack2(Wr[(size_t)(2 * kp) * 512 + gcol],
                           Wr[(size_t)(2 * kp + 1) * 512 + gcol]);
    }

    if (Wout) {
        for (int i = tid; i < 2048; i += nthr) {
            int k2 = i >> 5, oc = i & 31;
            wo2[k2][oc] = pack2(Wout[(size_t)(2 * k2) * 64 + (int)q * 32 + oc],
                                Wout[(size_t)(2 * k2 + 1) * 64 + (int)q * 32 + oc]);
        }
        if (tid < 32) bo_s[tid] = bout[(int)q * 32 + tid];
    }

    for (int i = tid; i < 512; i += nthr) h_s[0][i >> 7][i & 127] = 0.f;
    const uint32_t mbar = (uint32_t)__cvta_generic_to_shared(mbar_p);
    if (tid == 0)
        asm volatile("mbarrier.init.shared.b64 [%0], %1;\n" :: "r"(mbar), "r"(8u) : "memory");
    __syncthreads();

    const int pr = (tid >> 6) & 3, c4 = (tid & 63) * 4;
    const int pcol = (c4 >> 6) * 128 + (int)q * 64 + (c4 & 63);
    for (int s = 0; s < 7; s++) {
        if (tid < 256)
            cp_async16(&gbuf[s][pr][c4], gproj + ((size_t)(b0 + pr) * TT + s) * 512 + pcol);
        cp_async_commit();
    }
    cp_async_wait6();
    __syncthreads();
    cluster_sync_();

    const int r2 = (tid >> 6) & 3, jj = tid & 63;
    const int jg = (int)q * 64 + jj;
    const int lane = tid & 31;
    const int orow = (tid - 256) >> 5, oc = tid & 31;
    float c = 0.f;
    int p = 0;
    uint32_t par = 0;

    for (int t = 0; t < TT; t++) {
        const int st = t & 7;
        if (tid < 256 && t + 7 < TT)
            cp_async16(&gbuf[(t + 7) & 7][pr][c4],
                       gproj + ((size_t)(b0 + pr) * TT + t + 7) * 512 + pcol);
        cp_async_commit();

        if (tid < 256) {
            ull a[4], e[4];
#pragma unroll
            for (int r = 0; r < 4; r++) { a[r] = 0ull; e[r] = 0ull; }
            const float* h0p = h_s[p][0];
            const float* h1p = h_s[p][1];
            const float* h2p = h_s[p][2];
            const float* h3p = h_s[p][3];
#pragma unroll
            for (int kp = 0; kp < 64; kp += 2) {
                ulonglong2 u0 = *(const ulonglong2*)(h0p + 2 * kp);
                ulonglong2 u1 = *(const ulonglong2*)(h1p + 2 * kp);
                ulonglong2 u2 = *(const ulonglong2*)(h2p + 2 * kp);
                ulonglong2 u3 = *(const ulonglong2*)(h3p + 2 * kp);
                fma2(a[0], w2[kp], u0.x); fma2(e[0], w2[kp + 1], u0.y);
                fma2(a[1], w2[kp], u1.x); fma2(e[1], w2[kp + 1], u1.y);
                fma2(a[2], w2[kp], u2.x); fma2(e[2], w2[kp + 1], u2.y);
                fma2(a[3], w2[kp], u3.x); fma2(e[3], w2[kp + 1], u3.y);
            }
#pragma unroll
            for (int r = 0; r < 4; r++) {
                float2 f = unpack2(add2(a[r], e[r]));
                z_s[r][tid] = gbuf[st][r][tid] + (f.x + f.y);
            }
        }
        __syncthreads();

        if (tid < 256) {
            float zi = z_s[r2][jj];
            float zf = z_s[r2][64 + jj];
            float zg = z_s[r2][128 + jj];
            float zo = z_s[r2][192 + jj];
            c = fsig(zf) * c + fsig(zi) * fmaxf(zg, 0.f);
            float h = fsig(zo) * fmaxf(c, 0.f);
            float* own = &h_s[p ^ 1][r2][jg];
            *own = h;
            st_remote_f32(own, peer, h);
            if (hseq) hseq[((size_t)(b0 + r2) * TT + t) * 128 + jg] = h;
            __syncwarp();
            if (lane == 0) mbar_arrive_remote(mbar, peer);
        }
        else if (Wout && t > 0) {
            const ull* hp = (const ull*)&h_s[p][orow][0];
            ull oa = 0ull, ob = 0ull;
#pragma unroll
            for (int k2 = 0; k2 < 64; k2 += 2) {
                ulonglong2 hv = *(const ulonglong2*)&hp[k2];
                fma2(oa, wo2[k2][oc], hv.x);
                fma2(ob, wo2[k2 + 1][oc], hv.y);
            }
            float2 f = unpack2(add2(oa, ob));
            outp[((size_t)(b0 + orow) * TT + (t - 1)) * 64 + (int)q * 32 + oc] =
                f.x + f.y + bo_s[oc];
        }

        cp_async_wait6();
        __syncthreads();
        mbar_wait(mbar, par);
        par ^= 1;
        p ^= 1;
    }

    if (Wout && tid >= 256) {
        const ull* hp = (const ull*)&h_s[p][orow][0];
        ull oa = 0ull, ob = 0ull;
#pragma unroll
        for (int k2 = 0; k2 < 64; k2 += 2) {
            ulonglong2 hv = *(const ulonglong2*)&hp[k2];
            fma2(oa, wo2[k2][oc], hv.x);
            fma2(ob, wo2[k2 + 1][oc], hv.y);
        }
        float2 f = unpack2(add2(oa, ob));
        outp[((size_t)(b0 + orow) * TT + (TT - 1)) * 64 + (int)q * 32 + oc] =
            f.x + f.y + bo_s[oc];
    }
}

// ---------------- host orchestration ----------------------------------------
extern "C" void kernel_launch(void* const* d_in, const int* in_sizes, int n_in,
                              void* d_out, int out_size) {
    const float* x    = (const float*)d_in[0];
    const float* Wk1  = (const float*)d_in[1];
    const float* Wr1  = (const float*)d_in[2];
    const float* b1   = (const float*)d_in[3];
    const float* Wk2  = (const float*)d_in[4];
    const float* Wr2  = (const float*)d_in[5];
    const float* b2   = (const float*)d_in[6];
    const float* Wd1k = (const float*)d_in[7];
    const float* Wd1r = (const float*)d_in[8];
    const float* bd1  = (const float*)d_in[9];
    const float* Wd2k = (const float*)d_in[10];
    const float* Wd2r = (const float*)d_in[11];
    const float* bd2  = (const float*)d_in[12];
    const float* Wout = (const float*)d_in[13];
    const float* bout = (const float*)d_in[14];
    float* out = (float*)d_out;

    float *bufG, *h1, *d1, *z, *gd1;
    cudaGetSymbolAddress((void**)&bufG, g_bufG);
    cudaGetSymbolAddress((void**)&h1,  g_h1);
    cudaGetSymbolAddress((void**)&d1,  g_d1);
    cudaGetSymbolAddress((void**)&z,   g_z);
    cudaGetSymbolAddress((void**)&gd1, g_gd1);

    const int SMEM_L128 = 57600;
    const int SMEM_GEMM = 49152;
    cudaFuncSetAttribute(lstm128_kernel, cudaFuncAttributeMaxDynamicSharedMemorySize, SMEM_L128);
    cudaFuncSetAttribute(gemm_f32x2_kernel, cudaFuncAttributeMaxDynamicSharedMemorySize, SMEM_GEMM);

    dim3 blk(256);

    // 1) G1 = x @ Wk1 + b1                     [BT,512]
    gemm_f32x2_kernel<<<dim3(1024, 4), blk, SMEM_GEMM>>>(x, Wk1, b1, bufG, BT, 512, 64);
    // 2) encoder L1 recurrence -> h1           [BT,128]   (256 threads, no fusion)
    lstm128_kernel<<<128, 256, SMEM_L128>>>(bufG, Wr1, h1, nullptr, nullptr, nullptr);
    // 3) G2 = h1 @ Wk2 + b2                    [BT,256]
    gemm_f32x2_kernel<<<dim3(1024, 2), blk, SMEM_GEMM>>>(h1, Wk2, b2, bufG, BT, 256, 128);
    // 4) encoder L2 recurrence -> z (last h)   [256,64]
    lstm64_kernel<<<128, blk>>>(bufG, Wr2, nullptr, z, 0);
    // 5) Gd1 = z @ Wd1k + bd1 (constant/step)  [256,256]
    gemm_f32x2_kernel<<<dim3(2, 2), blk, SMEM_GEMM>>>(z, Wd1k, bd1, gd1, 256, 256, 64);
    // 6) decoder L1 recurrence -> d1           [BT,64]
    lstm64_kernel<<<128, blk>>>(gd1, Wd1r, d1, nullptr, 1);
    // 7) Gd2 = d1 @ Wd2k + bd2                 [BT,512]
    gemm_f32x2_kernel<<<dim3(1024, 4), blk, SMEM_GEMM>>>(d1, Wd2k, bd2, bufG, BT, 512, 64);
    // 8) decoder L2 recurrence + FUSED final dense -> out  [BT,64]  (384 threads)
    lstm128_kernel<<<128, 384, SMEM_L128>>>(bufG, Wd2r, nullptr, Wout, bout, out);
}

// round 12
// speedup vs baseline: 1.0917x; 1.0917x over previous
#include <cuda_runtime.h>
#include <cstdint>

#define BT 131072   // B*T = 256*512
#define TT 512

typedef unsigned long long ull;

// ---------------- scratch (device globals; no runtime allocation) ----------
__device__ float g_bufG[67108864];  // [BT,512]  G1 / G2 / Gd2 (reused)
__device__ float g_h1[16777216];    // [BT,128]
__device__ float g_d1[8388608];     // [BT,64]
__device__ float g_z[16384];        // [256,64]
__device__ float g_gd1[65536];      // [256,256]

// ---------------- packed f32x2 helpers --------------------------------------
__device__ __forceinline__ ull dup2(float x) {
    ull r; asm("mov.b64 %0, {%1, %1};" : "=l"(r) : "f"(x)); return r;
}
__device__ __forceinline__ ull pack2(float lo, float hi) {
    ull r; asm("mov.b64 %0, {%1, %2};" : "=l"(r) : "f"(lo), "f"(hi)); return r;
}
__device__ __forceinline__ float2 unpack2(ull v) {
    float2 f; asm("mov.b64 {%0, %1}, %2;" : "=f"(f.x), "=f"(f.y) : "l"(v)); return f;
}
__device__ __forceinline__ void fma2(ull& acc, ull a, ull b) {
    asm("fma.rn.f32x2 %0, %1, %2, %0;" : "+l"(acc) : "l"(a), "l"(b));
}
__device__ __forceinline__ ull add2(ull a, ull b) {
    ull d; asm("add.rn.f32x2 %0, %1, %2;" : "=l"(d) : "l"(a), "l"(b)); return d;
}

// fast sigmoid via single-MUFU tanh: sig(x) = 0.5*tanh(x/2) + 0.5
__device__ __forceinline__ float fsig(float x) {
    float t;
    asm("tanh.approx.f32 %0, %1;" : "=f"(t) : "f"(x * 0.5f));
    return fmaf(t, 0.5f, 0.5f);
}

// ---------------- misc helpers ----------------------------------------------
__device__ __forceinline__ void cp_async16(void* smem_dst, const void* gmem_src) {
    uint32_t s = (uint32_t)__cvta_generic_to_shared(smem_dst);
    asm volatile("cp.async.cg.shared.global [%0], [%1], 16;\n" :: "r"(s), "l"(gmem_src));
}
__device__ __forceinline__ void cp_async_commit() { asm volatile("cp.async.commit_group;\n"); }
__device__ __forceinline__ void cp_async_wait6()  { asm volatile("cp.async.wait_group 6;\n"); }
__device__ __forceinline__ void cp_async_wait0()  { asm volatile("cp.async.wait_group 0;\n"); }

__device__ __forceinline__ void cluster_sync_() {
    asm volatile("barrier.cluster.arrive.aligned;\n" ::: "memory");
    asm volatile("barrier.cluster.wait.aligned;\n" ::: "memory");
}
__device__ __forceinline__ void st_remote_f32(float* local_ptr, uint32_t peer, float v) {
    uint32_t la = (uint32_t)__cvta_generic_to_shared(local_ptr);
    uint32_t ra;
    asm("mapa.shared::cluster.u32 %0, %1, %2;\n" : "=r"(ra) : "r"(la), "r"(peer));
    asm volatile("st.shared::cluster.f32 [%0], %1;\n" :: "r"(ra), "f"(v) : "memory");
}
__device__ __forceinline__ void mbar_arrive_remote(uint32_t local_mbar, uint32_t peer) {
    uint32_t ra;
    asm("mapa.shared::cluster.u32 %0, %1, %2;\n" : "=r"(ra) : "r"(local_mbar), "r"(peer));
    asm volatile("mbarrier.arrive.release.cluster.shared::cluster.b64 _, [%0];\n"
                 :: "r"(ra) : "memory");
}
__device__ __forceinline__ void mbar_wait(uint32_t mbar, uint32_t parity) {
    asm volatile(
        "{\n\t.reg .pred P;\n"
        "WAITL_%=:\n\t"
        "mbarrier.try_wait.parity.acquire.cluster.shared::cta.b64 P, [%0], %1, 0x989680;\n\t"
        "@!P bra WAITL_%=;\n"
        "}" :: "r"(mbar), "r"(parity) : "memory");
}

// ---------------- bulk GEMM: C[M,N] = A[M,K] @ W[K,N] + bias ----------------
// 128x128 tile, BK=16, 256 threads, f32x2 accumulation. (R3/R9 proven version)
__global__ void __launch_bounds__(256)
gemm_f32x2_kernel(const float* __restrict__ A,
                  const float* __restrict__ W,
                  const float* __restrict__ bias,
                  float* __restrict__ C,
                  int M, int N, int K) {
    constexpr int BN = 128;
    __shared__ __align__(16) float As[2][16][128];
    __shared__ __align__(16) float Bs[2][16][BN];
    const int tid = threadIdx.x;
    const int m0 = blockIdx.x * 128, n0 = blockIdx.y * BN;
    const int tx = tid & 15, ty = tid >> 4;

    const int am = tid >> 1, ak = (tid & 1) * 8;
    const int nper = (16 * BN / 4) / 256;   // 2

    ull acc[8][4];
#pragma unroll
    for (int i = 0; i < 8; i++)
#pragma unroll
        for (int j = 0; j < 4; j++) acc[i][j] = 0ull;

    const int nk = K / 16;

    {
        const float* ap = A + (size_t)(m0 + am) * K + ak;
        float4 va = *(const float4*)ap;
        float4 vb = *(const float4*)(ap + 4);
#pragma unroll
        for (int q = 0; q < nper; q++) {
            int idx = tid * nper + q;
            int br = idx / (BN / 4), bc = (idx % (BN / 4)) * 4;
            cp_async16(&Bs[0][br][bc], W + (size_t)br * N + n0 + bc);
        }
        cp_async_commit();
        As[0][ak + 0][am] = va.x; As[0][ak + 1][am] = va.y;
        As[0][ak + 2][am] = va.z; As[0][ak + 3][am] = va.w;
        As[0][ak + 4][am] = vb.x; As[0][ak + 5][am] = vb.y;
        As[0][ak + 6][am] = vb.z; As[0][ak + 7][am] = vb.w;
        cp_async_wait0();
        __syncthreads();
    }

    for (int kt = 0; kt < nk; kt++) {
        const int p = kt & 1;
        const bool more = (kt + 1) < nk;
        float4 va, vb;
        if (more) {
            const float* ap = A + (size_t)(m0 + am) * K + (kt + 1) * 16 + ak;
            va = *(const float4*)ap;
            vb = *(const float4*)(ap + 4);
#pragma unroll
            for (int q = 0; q < nper; q++) {
                int idx = tid * nper + q;
                int br = idx / (BN / 4), bc = (idx % (BN / 4)) * 4;
                cp_async16(&Bs[p ^ 1][br][bc], W + (size_t)((kt + 1) * 16 + br) * N + n0 + bc);
            }
        }
        cp_async_commit();

#pragma unroll
        for (int k = 0; k < 16; k++) {
            float4 a0 = *(const float4*)&As[p][k][ty * 4];
            float4 a1 = *(const float4*)&As[p][k][64 + ty * 4];
            ulonglong2 b0v = *(const ulonglong2*)&Bs[p][k][tx * 4];
            ulonglong2 b1v = *(const ulonglong2*)&Bs[p][k][64 + tx * 4];
            float av[8] = {a0.x, a0.y, a0.z, a0.w, a1.x, a1.y, a1.z, a1.w};
#pragma unroll
            for (int i = 0; i < 8; i++) {
                ull aa = dup2(av[i]);
                fma2(acc[i][0], aa, b0v.x);
                fma2(acc[i][1], aa, b0v.y);
                fma2(acc[i][2], aa, b1v.x);
                fma2(acc[i][3], aa, b1v.y);
            }
        }

        if (more) {
            As[p ^ 1][ak + 0][am] = va.x; As[p ^ 1][ak + 1][am] = va.y;
            As[p ^ 1][ak + 2][am] = va.z; As[p ^ 1][ak + 3][am] = va.w;
            As[p ^ 1][ak + 4][am] = vb.x; As[p ^ 1][ak + 5][am] = vb.y;
            As[p ^ 1][ak + 6][am] = vb.z; As[p ^ 1][ak + 7][am] = vb.w;
        }
        cp_async_wait0();
        __syncthreads();
    }

    ull bz[4];
    bz[0] = *(const ull*)&bias[n0 + tx * 4];
    bz[1] = *(const ull*)&bias[n0 + tx * 4 + 2];
    bz[2] = *(const ull*)&bias[n0 + 64 + tx * 4];
    bz[3] = *(const ull*)&bias[n0 + 64 + tx * 4 + 2];
#pragma unroll
    for (int i = 0; i < 8; i++) {
        int row = m0 + ((i < 4) ? (ty * 4 + i) : (64 + ty * 4 + i - 4));
        ulonglong2 o0;
        o0.x = add2(acc[i][0], bz[0]);
        o0.y = add2(acc[i][1], bz[1]);
        *(ulonglong2*)&C[(size_t)row * N + n0 + tx * 4] = o0;
        ulonglong2 o1;
        o1.x = add2(acc[i][2], bz[2]);
        o1.y = add2(acc[i][3], bz[3]);
        *(ulonglong2*)&C[(size_t)row * N + n0 + 64 + tx * 4] = o1;
    }
}

// ---------------- LSTM recurrence, H=64 (R4 structure) ----------------------
__global__ void __launch_bounds__(256)
lstm64_kernel(const float* __restrict__ gproj, // [BT,256] or [256,256] if constProj
              const float* __restrict__ Wr,    // [64,256]
              float* __restrict__ hseq,        // [BT,64] or null
              float* __restrict__ hlast,       // [256,64] or null
              int constProj) {
    __shared__ __align__(16) float h_s[2][2][64];
    __shared__ __align__(16) float gbuf[8][2][256];   // 16KB

    const int tid = threadIdx.x;
    const int b0 = blockIdx.x * 2;
    const int w = tid >> 5, lane = tid & 31;
    const int r = w >> 2;                    // row 0/1
    const int j = (w & 3) * 16 + (lane & 15);
    const int kh = lane >> 4;                // k half: k in [kh*32, kh*32+32)

    ull w2[64];
#pragma unroll
    for (int g = 0; g < 4; g++)
#pragma unroll
        for (int kp = 0; kp < 16; kp++) {
            int k = kh * 32 + 2 * kp;
            w2[g * 16 + kp] = pack2(Wr[k * 256 + g * 64 + j],
                                    Wr[(k + 1) * 256 + g * 64 + j]);
        }

    if (tid < 128) h_s[0][tid >> 6][tid & 63] = 0.f;

    const int pr = tid >> 6, c4 = (tid & 63) * 4;
    float gc[4] = {0.f, 0.f, 0.f, 0.f};
    if (constProj) {
#pragma unroll
        for (int g = 0; g < 4; g++)
            gc[g] = gproj[(size_t)(b0 + r) * 256 + g * 64 + j];
    } else {
        for (int s = 0; s < 7; s++) {
            if (tid < 128)
                cp_async16(&gbuf[s][pr][c4], gproj + ((size_t)(b0 + pr) * TT + s) * 256 + c4);
            cp_async_commit();
        }
        cp_async_wait6();
    }
    __syncthreads();

    float c = 0.f;
    float hcur = 0.f;
    int p = 0;

    for (int t = 0; t < TT; t++) {
        const int st = t & 7;
        if (!constProj) {
            if (tid < 128 && t + 7 < TT)
                cp_async16(&gbuf[(t + 7) & 7][pr][c4],
                           gproj + ((size_t)(b0 + pr) * TT + t + 7) * 256 + c4);
            cp_async_commit();
        }

        ull hv[16];
        const float* hp = &h_s[p][r][kh * 32];
#pragma unroll
        for (int q = 0; q < 8; q++) {
            ulonglong2 v = *(const ulonglong2*)(hp + q * 4);
            hv[q * 2] = v.x; hv[q * 2 + 1] = v.y;
        }

        ull ae[4] = {0ull, 0ull, 0ull, 0ull};
        ull ao[4] = {0ull, 0ull, 0ull, 0ull};
#pragma unroll
        for (int kp = 0; kp < 16; kp += 2) {
#pragma unroll
            for (int g = 0; g < 4; g++) {
                fma2(ae[g], w2[g * 16 + kp], hv[kp]);
                fma2(ao[g], w2[g * 16 + kp + 1], hv[kp + 1]);
            }
        }
        float s[4];
#pragma unroll
        for (int g = 0; g < 4; g++) {
            float2 f = unpack2(add2(ae[g], ao[g]));
            s[g] = f.x + f.y;
            s[g] += __shfl_xor_sync(0xffffffffu, s[g], 16);
        }

        float zi, zf, zg, zo;
        if (constProj) {
            zi = s[0] + gc[0]; zf = s[1] + gc[1]; zg = s[2] + gc[2]; zo = s[3] + gc[3];
        } else {
            zi = s[0] + gbuf[st][r][j];
            zf = s[1] + gbuf[st][r][64 + j];
            zg = s[2] + gbuf[st][r][128 + j];
            zo = s[3] + gbuf[st][r][192 + j];
        }
        c = fsig(zf) * c + fsig(zi) * fmaxf(zg, 0.f);
        hcur = fsig(zo) * fmaxf(c, 0.f);
        if (kh == 0) h_s[p ^ 1][r][j] = hcur;
        else if (hseq) hseq[((size_t)(b0 + r) * TT + t) * 64 + j] = hcur;

        if (!constProj) cp_async_wait6();
        __syncthreads();
        p ^= 1;
    }
    if (hlast && kh == 0)
        hlast[(size_t)(b0 + r) * 64 + j] = hcur;
}

// ---------------- LSTM recurrence, H=128 (R9: R3 256-thr core + fused out) --
__global__ void __launch_bounds__(384) __cluster_dims__(2, 1, 1)
lstm128_kernel(const float* __restrict__ gproj, // [BT,512]
               const float* __restrict__ Wr,    // [128,512]
               float* __restrict__ hseq,        // [BT,128] or null
               const float* __restrict__ Wout,  // [128,64] or null (fused out)
               const float* __restrict__ bout,  // [64]
               float* __restrict__ outp) {      // [BT,64]
    extern __shared__ __align__(16) float sm[];
    float (*h_s)[4][128]  = (float (*)[4][128])sm;           // [2][4][128]
    float (*z_s)[256]     = (float (*)[256])(sm + 1024);     // [4][256]
    float (*gbuf)[4][256] = (float (*)[4][256])(sm + 2048);  // [8][4][256]
    ull (*wo2)[32]        = (ull (*)[32])(sm + 10240);       // [64][32]
    float* bo_s           = sm + 14336;                      // [32]
    ull* mbar_p           = (ull*)(sm + 14368);

    const int tid = threadIdx.x;
    const int nthr = blockDim.x;
    uint32_t q;
    asm("mov.u32 %0, %%cluster_ctarank;" : "=r"(q));
    const uint32_t peer = q ^ 1u;
    const int b0 = (blockIdx.x >> 1) * 4;
    const int gcol = ((tid >> 6) & 3) * 128 + (int)q * 64 + (tid & 63);

    ull w2[64];
    if (tid < 256) {
#pragma unroll
        for (int kp = 0; kp < 64; kp++)
            w2[kp] = pack2(Wr[(size_t)(2 * kp) * 512 + gcol],
                           Wr[(size_t)(2 * kp + 1) * 512 + gcol]);
    }

    if (Wout) {
        for (int i = tid; i < 2048; i += nthr) {
            int k2 = i >> 5, oc = i & 31;
            wo2[k2][oc] = pack2(Wout[(size_t)(2 * k2) * 64 + (int)q * 32 + oc],
                                Wout[(size_t)(2 * k2 + 1) * 64 + (int)q * 32 + oc]);
        }
        if (tid < 32) bo_s[tid] = bout[(int)q * 32 + tid];
    }

    for (int i = tid; i < 512; i += nthr) h_s[0][i >> 7][i & 127] = 0.f;
    const uint32_t mbar = (uint32_t)__cvta_generic_to_shared(mbar_p);
    if (tid == 0)
        asm volatile("mbarrier.init.shared.b64 [%0], %1;\n" :: "r"(mbar), "r"(8u) : "memory");
    __syncthreads();

    const int pr = (tid >> 6) & 3, c4 = (tid & 63) * 4;
    const int pcol = (c4 >> 6) * 128 + (int)q * 64 + (c4 & 63);
    for (int s = 0; s < 7; s++) {
        if (tid < 256)
            cp_async16(&gbuf[s][pr][c4], gproj + ((size_t)(b0 + pr) * TT + s) * 512 + pcol);
        cp_async_commit();
    }
    cp_async_wait6();
    __syncthreads();
    cluster_sync_();

    const int r2 = (tid >> 6) & 3, jj = tid & 63;
    const int jg = (int)q * 64 + jj;
    const int lane = tid & 31;
    const int orow = (tid - 256) >> 5, oc = tid & 31;
    float c = 0.f;
    int p = 0;
    uint32_t par = 0;

    for (int t = 0; t < TT; t++) {
        const int st = t & 7;
        if (tid < 256 && t + 7 < TT)
            cp_async16(&gbuf[(t + 7) & 7][pr][c4],
                       gproj + ((size_t)(b0 + pr) * TT + t + 7) * 512 + pcol);
        cp_async_commit();

        if (tid < 256) {
            ull a[4], e[4];
#pragma unroll
            for (int r = 0; r < 4; r++) { a[r] = 0ull; e[r] = 0ull; }
            const float* h0p = h_s[p][0];
            const float* h1p = h_s[p][1];
            const float* h2p = h_s[p][2];
            const float* h3p = h_s[p][3];
#pragma unroll
            for (int kp = 0; kp < 64; kp += 2) {
                ulonglong2 u0 = *(const ulonglong2*)(h0p + 2 * kp);
                ulonglong2 u1 = *(const ulonglong2*)(h1p + 2 * kp);
                ulonglong2 u2 = *(const ulonglong2*)(h2p + 2 * kp);
                ulonglong2 u3 = *(const ulonglong2*)(h3p + 2 * kp);
                fma2(a[0], w2[kp], u0.x); fma2(e[0], w2[kp + 1], u0.y);
                fma2(a[1], w2[kp], u1.x); fma2(e[1], w2[kp + 1], u1.y);
                fma2(a[2], w2[kp], u2.x); fma2(e[2], w2[kp + 1], u2.y);
                fma2(a[3], w2[kp], u3.x); fma2(e[3], w2[kp + 1], u3.y);
            }
#pragma unroll
            for (int r = 0; r < 4; r++) {
                float2 f = unpack2(add2(a[r], e[r]));
                z_s[r][tid] = gbuf[st][r][tid] + (f.x + f.y);
            }
        }
        __syncthreads();

        if (tid < 256) {
            float zi = z_s[r2][jj];
            float zf = z_s[r2][64 + jj];
            float zg = z_s[r2][128 + jj];
            float zo = z_s[r2][192 + jj];
            c = fsig(zf) * c + fsig(zi) * fmaxf(zg, 0.f);
            float h = fsig(zo) * fmaxf(c, 0.f);
            float* own = &h_s[p ^ 1][r2][jg];
            *own = h;
            st_remote_f32(own, peer, h);
            if (hseq) hseq[((size_t)(b0 + r2) * TT + t) * 128 + jg] = h;
            __syncwarp();
            if (lane == 0) mbar_arrive_remote(mbar, peer);
        }
        else if (Wout && t > 0) {
            const ull* hp = (const ull*)&h_s[p][orow][0];
            ull oa = 0ull, ob = 0ull;
#pragma unroll
            for (int k2 = 0; k2 < 64; k2 += 2) {
                ulonglong2 hv = *(const ulonglong2*)&hp[k2];
                fma2(oa, wo2[k2][oc], hv.x);
                fma2(ob, wo2[k2 + 1][oc], hv.y);
            }
            float2 f = unpack2(add2(oa, ob));
            outp[((size_t)(b0 + orow) * TT + (t - 1)) * 64 + (int)q * 32 + oc] =
                f.x + f.y + bo_s[oc];
        }

        cp_async_wait6();
        __syncthreads();
        mbar_wait(mbar, par);
        par ^= 1;
        p ^= 1;
    }

    if (Wout && tid >= 256) {
        const ull* hp = (const ull*)&h_s[p][orow][0];
        ull oa = 0ull, ob = 0ull;
#pragma unroll
        for (int k2 = 0; k2 < 64; k2 += 2) {
            ulonglong2 hv = *(const ulonglong2*)&hp[k2];
            fma2(oa, wo2[k2][oc], hv.x);
            fma2(ob, wo2[k2 + 1][oc], hv.y);
        }
        float2 f = unpack2(add2(oa, ob));
        outp[((size_t)(b0 + orow) * TT + (TT - 1)) * 64 + (int)q * 32 + oc] =
            f.x + f.y + bo_s[oc];
    }
}

// ---------------- host orchestration ----------------------------------------
extern "C" void kernel_launch(void* const* d_in, const int* in_sizes, int n_in,
                              void* d_out, int out_size) {
    const float* x    = (const float*)d_in[0];
    const float* Wk1  = (const float*)d_in[1];
    const float* Wr1  = (const float*)d_in[2];
    const float* b1   = (const float*)d_in[3];
    const float* Wk2  = (const float*)d_in[4];
    const float* Wr2  = (const float*)d_in[5];
    const float* b2   = (const float*)d_in[6];
    const float* Wd1k = (const float*)d_in[7];
    const float* Wd1r = (const float*)d_in[8];
    const float* bd1  = (const float*)d_in[9];
    const float* Wd2k = (const float*)d_in[10];
    const float* Wd2r = (const float*)d_in[11];
    const float* bd2  = (const float*)d_in[12];
    const float* Wout = (const float*)d_in[13];
    const float* bout = (const float*)d_in[14];
    float* out = (float*)d_out;

    float *bufG, *h1, *d1, *z, *gd1;
    cudaGetSymbolAddress((void**)&bufG, g_bufG);
    cudaGetSymbolAddress((void**)&h1,  g_h1);
    cudaGetSymbolAddress((void**)&d1,  g_d1);
    cudaGetSymbolAddress((void**)&z,   g_z);
    cudaGetSymbolAddress((void**)&gd1, g_gd1);

    const int SMEM_L128 = 57600;
    cudaFuncSetAttribute(lstm128_kernel, cudaFuncAttributeMaxDynamicSharedMemorySize, SMEM_L128);

    dim3 blk(256);

    // 1) G1 = x @ Wk1 + b1                     [BT,512]
    gemm_f32x2_kernel<<<dim3(1024, 4), blk>>>(x, Wk1, b1, bufG, BT, 512, 64);
    // 2) encoder L1 recurrence -> h1           [BT,128]   (256 threads, no fusion)
    lstm128_kernel<<<128, 256, SMEM_L128>>>(bufG, Wr1, h1, nullptr, nullptr, nullptr);
    // 3) G2 = h1 @ Wk2 + b2                    [BT,256]
    gemm_f32x2_kernel<<<dim3(1024, 2), blk>>>(h1, Wk2, b2, bufG, BT, 256, 128);
    // 4) encoder L2 recurrence -> z (last h)   [256,64]
    lstm64_kernel<<<128, blk>>>(bufG, Wr2, nullptr, z, 0);
    // 5) Gd1 = z @ Wd1k + bd1 (constant/step)  [256,256]
    gemm_f32x2_kernel<<<dim3(2, 2), blk>>>(z, Wd1k, bd1, gd1, 256, 256, 64);
    // 6) decoder L1 recurrence -> d1           [BT,64]
    lstm64_kernel<<<128, blk>>>(gd1, Wd1r, d1, nullptr, 1);
    // 7) Gd2 = d1 @ Wd2k + bd2                 [BT,512]
    gemm_f32x2_kernel<<<dim3(1024, 4), blk>>>(d1, Wd2k, bd2, bufG, BT, 512, 64);
    // 8) decoder L2 recurrence + FUSED final dense -> out  [BT,64]  (384 threads)
    lstm128_kernel<<<128, 384, SMEM_L128>>>(bufG, Wd2r, nullptr, Wout, bout, out);
}

// round 13
// speedup vs baseline: 1.1058x; 1.0129x over previous
#include <cuda_runtime.h>
#include <cstdint>

#define BT 131072   // B*T = 256*512
#define TT 512

typedef unsigned long long ull;

// ---------------- scratch (device globals; no runtime allocation) ----------
__device__ float g_bufG[67108864];  // [BT,512]  G1 / G2 / Gd2 (reused)
__device__ float g_h1[16777216];    // [BT,128]
__device__ float g_d1[8388608];     // [BT,64]
__device__ float g_z[16384];        // [256,64]

// ---------------- packed f32x2 helpers --------------------------------------
__device__ __forceinline__ ull dup2(float x) {
    ull r; asm("mov.b64 %0, {%1, %1};" : "=l"(r) : "f"(x)); return r;
}
__device__ __forceinline__ ull pack2(float lo, float hi) {
    ull r; asm("mov.b64 %0, {%1, %2};" : "=l"(r) : "f"(lo), "f"(hi)); return r;
}
__device__ __forceinline__ float2 unpack2(ull v) {
    float2 f; asm("mov.b64 {%0, %1}, %2;" : "=f"(f.x), "=f"(f.y) : "l"(v)); return f;
}
__device__ __forceinline__ void fma2(ull& acc, ull a, ull b) {
    asm("fma.rn.f32x2 %0, %1, %2, %0;" : "+l"(acc) : "l"(a), "l"(b));
}
__device__ __forceinline__ ull add2(ull a, ull b) {
    ull d; asm("add.rn.f32x2 %0, %1, %2;" : "=l"(d) : "l"(a), "l"(b)); return d;
}

// fast sigmoid via single-MUFU tanh: sig(x) = 0.5*tanh(x/2) + 0.5
__device__ __forceinline__ float fsig(float x) {
    float t;
    asm("tanh.approx.f32 %0, %1;" : "=f"(t) : "f"(x * 0.5f));
    return fmaf(t, 0.5f, 0.5f);
}

// ---------------- misc helpers ----------------------------------------------
__device__ __forceinline__ void cp_async16(void* smem_dst, const void* gmem_src) {
    uint32_t s = (uint32_t)__cvta_generic_to_shared(smem_dst);
    asm volatile("cp.async.cg.shared.global [%0], [%1], 16;\n" :: "r"(s), "l"(gmem_src));
}
__device__ __forceinline__ void cp_async_commit() { asm volatile("cp.async.commit_group;\n"); }
__device__ __forceinline__ void cp_async_wait6()  { asm volatile("cp.async.wait_group 6;\n"); }
__device__ __forceinline__ void cp_async_wait0()  { asm volatile("cp.async.wait_group 0;\n"); }

__device__ __forceinline__ void cluster_sync_() {
    asm volatile("barrier.cluster.arrive.aligned;\n" ::: "memory");
    asm volatile("barrier.cluster.wait.aligned;\n" ::: "memory");
}
__device__ __forceinline__ void st_remote_f32(float* local_ptr, uint32_t peer, float v) {
    uint32_t la = (uint32_t)__cvta_generic_to_shared(local_ptr);
    uint32_t ra;
    asm("mapa.shared::cluster.u32 %0, %1, %2;\n" : "=r"(ra) : "r"(la), "r"(peer));
    asm volatile("st.shared::cluster.f32 [%0], %1;\n" :: "r"(ra), "f"(v) : "memory");
}
__device__ __forceinline__ void mbar_arrive_remote(uint32_t local_mbar, uint32_t peer) {
    uint32_t ra;
    asm("mapa.shared::cluster.u32 %0, %1, %2;\n" : "=r"(ra) : "r"(local_mbar), "r"(peer));
    asm volatile("mbarrier.arrive.release.cluster.shared::cluster.b64 _, [%0];\n"
                 :: "r"(ra) : "memory");
}
__device__ __forceinline__ void mbar_wait(uint32_t mbar, uint32_t parity) {
    asm volatile(
        "{\n\t.reg .pred P;\n"
        "WAITL_%=:\n\t"
        "mbarrier.try_wait.parity.acquire.cluster.shared::cta.b64 P, [%0], %1, 0x989680;\n\t"
        "@!P bra WAITL_%=;\n"
        "}" :: "r"(mbar), "r"(parity) : "memory");
}

// ---------------- bulk GEMM: C[M,N] = A[M,K] @ W[K,N] + bias ----------------
// 128x128 tile, BK=16, 256 threads, f32x2 accumulation. (R3/R9 proven version)
__global__ void __launch_bounds__(256)
gemm_f32x2_kernel(const float* __restrict__ A,
                  const float* __restrict__ W,
                  const float* __restrict__ bias,
                  float* __restrict__ C,
                  int M, int N, int K) {
    constexpr int BN = 128;
    __shared__ __align__(16) float As[2][16][128];
    __shared__ __align__(16) float Bs[2][16][BN];
    const int tid = threadIdx.x;
    const int m0 = blockIdx.x * 128, n0 = blockIdx.y * BN;
    const int tx = tid & 15, ty = tid >> 4;

    const int am = tid >> 1, ak = (tid & 1) * 8;
    const int nper = (16 * BN / 4) / 256;   // 2

    ull acc[8][4];
#pragma unroll
    for (int i = 0; i < 8; i++)
#pragma unroll
        for (int j = 0; j < 4; j++) acc[i][j] = 0ull;

    const int nk = K / 16;

    {
        const float* ap = A + (size_t)(m0 + am) * K + ak;
        float4 va = *(const float4*)ap;
        float4 vb = *(const float4*)(ap + 4);
#pragma unroll
        for (int q = 0; q < nper; q++) {
            int idx = tid * nper + q;
            int br = idx / (BN / 4), bc = (idx % (BN / 4)) * 4;
            cp_async16(&Bs[0][br][bc], W + (size_t)br * N + n0 + bc);
        }
        cp_async_commit();
        As[0][ak + 0][am] = va.x; As[0][ak + 1][am] = va.y;
        As[0][ak + 2][am] = va.z; As[0][ak + 3][am] = va.w;
        As[0][ak + 4][am] = vb.x; As[0][ak + 5][am] = vb.y;
        As[0][ak + 6][am] = vb.z; As[0][ak + 7][am] = vb.w;
        cp_async_wait0();
        __syncthreads();
    }

    for (int kt = 0; kt < nk; kt++) {
        const int p = kt & 1;
        const bool more = (kt + 1) < nk;
        float4 va, vb;
        if (more) {
            const float* ap = A + (size_t)(m0 + am) * K + (kt + 1) * 16 + ak;
            va = *(const float4*)ap;
            vb = *(const float4*)(ap + 4);
#pragma unroll
            for (int q = 0; q < nper; q++) {
                int idx = tid * nper + q;
                int br = idx / (BN / 4), bc = (idx % (BN / 4)) * 4;
                cp_async16(&Bs[p ^ 1][br][bc], W + (size_t)((kt + 1) * 16 + br) * N + n0 + bc);
            }
        }
        cp_async_commit();

#pragma unroll
        for (int k = 0; k < 16; k++) {
            float4 a0 = *(const float4*)&As[p][k][ty * 4];
            float4 a1 = *(const float4*)&As[p][k][64 + ty * 4];
            ulonglong2 b0v = *(const ulonglong2*)&Bs[p][k][tx * 4];
            ulonglong2 b1v = *(const ulonglong2*)&Bs[p][k][64 + tx * 4];
            float av[8] = {a0.x, a0.y, a0.z, a0.w, a1.x, a1.y, a1.z, a1.w};
#pragma unroll
            for (int i = 0; i < 8; i++) {
                ull aa = dup2(av[i]);
                fma2(acc[i][0], aa, b0v.x);
                fma2(acc[i][1], aa, b0v.y);
                fma2(acc[i][2], aa, b1v.x);
                fma2(acc[i][3], aa, b1v.y);
            }
        }

        if (more) {
            As[p ^ 1][ak + 0][am] = va.x; As[p ^ 1][ak + 1][am] = va.y;
            As[p ^ 1][ak + 2][am] = va.z; As[p ^ 1][ak + 3][am] = va.w;
            As[p ^ 1][ak + 4][am] = vb.x; As[p ^ 1][ak + 5][am] = vb.y;
            As[p ^ 1][ak + 6][am] = vb.z; As[p ^ 1][ak + 7][am] = vb.w;
        }
        cp_async_wait0();
        __syncthreads();
    }

    ull bz[4];
    bz[0] = *(const ull*)&bias[n0 + tx * 4];
    bz[1] = *(const ull*)&bias[n0 + tx * 4 + 2];
    bz[2] = *(const ull*)&bias[n0 + 64 + tx * 4];
    bz[3] = *(const ull*)&bias[n0 + 64 + tx * 4 + 2];
#pragma unroll
    for (int i = 0; i < 8; i++) {
        int row = m0 + ((i < 4) ? (ty * 4 + i) : (64 + ty * 4 + i - 4));
        ulonglong2 o0;
        o0.x = add2(acc[i][0], bz[0]);
        o0.y = add2(acc[i][1], bz[1]);
        *(ulonglong2*)&C[(size_t)row * N + n0 + tx * 4] = o0;
        ulonglong2 o1;
        o1.x = add2(acc[i][2], bz[2]);
        o1.y = add2(acc[i][3], bz[3]);
        *(ulonglong2*)&C[(size_t)row * N + n0 + 64 + tx * 4] = o1;
    }
}

// ---------------- LSTM recurrence, H=64; 1 row/CTA, 128 threads, 2 CTA/SM ---
// grid = 256 CTAs. Thread = (h-index j in 0..63, k-half kh). Same reg-weight
// inner loop as R4; barrier is 4 warps. constProj (zin != null) fuses the
// per-row projection gc = bd + z[row] @ Wk in the prologue (replaces gemm#5).
__global__ void __launch_bounds__(128)
lstm64_kernel(const float* __restrict__ gproj, // [BT,256] streaming, or null
              const float* __restrict__ Wr,    // [64,256]
              float* __restrict__ hseq,        // [BT,64] or null
              float* __restrict__ hlast,       // [256,64] or null
              const float* __restrict__ zin,   // [256,64] constProj input or null
              const float* __restrict__ Wk,    // [64,256] constProj proj weights
              const float* __restrict__ bd) {  // [256]    constProj bias
    __shared__ __align__(16) float h_s[2][64];
    __shared__ __align__(16) float gbuf[8][256];   // 8KB

    const int tid = threadIdx.x;
    const int b0 = blockIdx.x;               // batch row
    const int w = tid >> 5, lane = tid & 31;
    const int j = w * 16 + (lane & 15);      // h-index 0..63
    const int kh = lane >> 4;                // k half: k in [kh*32, kh*32+32)
    const bool constProj = (zin != nullptr);

    // weights: all 4 gates for column j, 16 k-pairs in this thread's half
    ull w2[64];
#pragma unroll
    for (int g = 0; g < 4; g++)
#pragma unroll
        for (int kp = 0; kp < 16; kp++) {
            int k = kh * 32 + 2 * kp;
            w2[g * 16 + kp] = pack2(Wr[k * 256 + g * 64 + j],
                                    Wr[(k + 1) * 256 + g * 64 + j]);
        }

    if (tid < 64) h_s[0][tid] = 0.f;

    const int c4 = (tid & 63) * 4;           // prefetch mapping (tid<64)
    float gc[4] = {0.f, 0.f, 0.f, 0.f};
    if (constProj) {
        // fused: gc = bd + z[b0] @ Wk (columns g*64+j)
#pragma unroll
        for (int g = 0; g < 4; g++) gc[g] = bd[g * 64 + j];
        for (int k = 0; k < 64; k++) {
            float zv = __ldg(&zin[(size_t)b0 * 64 + k]);
#pragma unroll
            for (int g = 0; g < 4; g++)
                gc[g] = fmaf(zv, Wk[k * 256 + g * 64 + j], gc[g]);
        }
    } else {
        for (int s = 0; s < 7; s++) {
            if (tid < 64)
                cp_async16(&gbuf[s][c4], gproj + ((size_t)b0 * TT + s) * 256 + c4);
            cp_async_commit();
        }
        cp_async_wait6();
    }
    __syncthreads();

    float c = 0.f;
    float hcur = 0.f;
    int p = 0;

    for (int t = 0; t < TT; t++) {
        const int st = t & 7;
        if (!constProj) {
            if (tid < 64 && t + 7 < TT)
                cp_async16(&gbuf[(t + 7) & 7][c4],
                           gproj + ((size_t)b0 * TT + t + 7) * 256 + c4);
            cp_async_commit();
        }

        // load this thread's 32-k half of h (broadcast LDS)
        ull hv[16];
        const float* hp = &h_s[p][kh * 32];
#pragma unroll
        for (int q = 0; q < 8; q++) {
            ulonglong2 v = *(const ulonglong2*)(hp + q * 4);
            hv[q * 2] = v.x; hv[q * 2 + 1] = v.y;
        }

        // 4 gate partial dots (even/odd kp chains for ILP)
        ull ae[4] = {0ull, 0ull, 0ull, 0ull};
        ull ao[4] = {0ull, 0ull, 0ull, 0ull};
#pragma unroll
        for (int kp = 0; kp < 16; kp += 2) {
#pragma unroll
            for (int g = 0; g < 4; g++) {
                fma2(ae[g], w2[g * 16 + kp], hv[kp]);
                fma2(ao[g], w2[g * 16 + kp + 1], hv[kp + 1]);
            }
        }
        float s[4];
#pragma unroll
        for (int g = 0; g < 4; g++) {
            float2 f = unpack2(add2(ae[g], ao[g]));
            s[g] = f.x + f.y;
            s[g] += __shfl_xor_sync(0xffffffffu, s[g], 16);
        }

        float zi, zf, zg, zo;
        if (constProj) {
            zi = s[0] + gc[0]; zf = s[1] + gc[1]; zg = s[2] + gc[2]; zo = s[3] + gc[3];
        } else {
            zi = s[0] + gbuf[st][j];
            zf = s[1] + gbuf[st][64 + j];
            zg = s[2] + gbuf[st][128 + j];
            zo = s[3] + gbuf[st][192 + j];
        }
        c = fsig(zf) * c + fsig(zi) * fmaxf(zg, 0.f);
        hcur = fsig(zo) * fmaxf(c, 0.f);
        if (kh == 0) h_s[p ^ 1][j] = hcur;
        else if (hseq) hseq[((size_t)b0 * TT + t) * 64 + j] = hcur;

        if (!constProj) cp_async_wait6();
        __syncthreads();
        p ^= 1;
    }
    if (hlast && kh == 0)
        hlast[(size_t)b0 * 64 + j] = hcur;
}

// ---------------- LSTM recurrence, H=128 (R9: R3 256-thr core + fused out) --
__global__ void __launch_bounds__(384) __cluster_dims__(2, 1, 1)
lstm128_kernel(const float* __restrict__ gproj, // [BT,512]
               const float* __restrict__ Wr,    // [128,512]
               float* __restrict__ hseq,        // [BT,128] or null
               const float* __restrict__ Wout,  // [128,64] or null (fused out)
               const float* __restrict__ bout,  // [64]
               float* __restrict__ outp) {      // [BT,64]
    extern __shared__ __align__(16) float sm[];
    float (*h_s)[4][128]  = (float (*)[4][128])sm;           // [2][4][128]
    float (*z_s)[256]     = (float (*)[256])(sm + 1024);     // [4][256]
    float (*gbuf)[4][256] = (float (*)[4][256])(sm + 2048);  // [8][4][256]
    ull (*wo2)[32]        = (ull (*)[32])(sm + 10240);       // [64][32]
    float* bo_s           = sm + 14336;                      // [32]
    ull* mbar_p           = (ull*)(sm + 14368);

    const int tid = threadIdx.x;
    const int nthr = blockDim.x;
    uint32_t q;
    asm("mov.u32 %0, %%cluster_ctarank;" : "=r"(q));
    const uint32_t peer = q ^ 1u;
    const int b0 = (blockIdx.x >> 1) * 4;
    const int gcol = ((tid >> 6) & 3) * 128 + (int)q * 64 + (tid & 63);

    ull w2[64];
    if (tid < 256) {
#pragma unroll
        for (int kp = 0; kp < 64; kp++)
            w2[kp] = pack2(Wr[(size_t)(2 * kp) * 512 + gcol],
                           Wr[(size_t)(2 * kp + 1) * 512 + gcol]);
    }

    if (Wout) {
        for (int i = tid; i < 2048; i += nthr) {
            int k2 = i >> 5, oc = i & 31;
            wo2[k2][oc] = pack2(Wout[(size_t)(2 * k2) * 64 + (int)q * 32 + oc],
                                Wout[(size_t)(2 * k2 + 1) * 64 + (int)q * 32 + oc]);
        }
        if (tid < 32) bo_s[tid] = bout[(int)q * 32 + tid];
    }

    for (int i = tid; i < 512; i += nthr) h_s[0][i >> 7][i & 127] = 0.f;
    const uint32_t mbar = (uint32_t)__cvta_generic_to_shared(mbar_p);
    if (tid == 0)
        asm volatile("mbarrier.init.shared.b64 [%0], %1;\n" :: "r"(mbar), "r"(8u) : "memory");
    __syncthreads();

    const int pr = (tid >> 6) & 3, c4 = (tid & 63) * 4;
    const int pcol = (c4 >> 6) * 128 + (int)q * 64 + (c4 & 63);
    for (int s = 0; s < 7; s++) {
        if (tid < 256)
            cp_async16(&gbuf[s][pr][c4], gproj + ((size_t)(b0 + pr) * TT + s) * 512 + pcol);
        cp_async_commit();
    }
    cp_async_wait6();
    __syncthreads();
    cluster_sync_();

    const int r2 = (tid >> 6) & 3, jj = tid & 63;
    const int jg = (int)q * 64 + jj;
    const int lane = tid & 31;
    const int orow = (tid - 256) >> 5, oc = tid & 31;
    float c = 0.f;
    int p = 0;
    uint32_t par = 0;

    for (int t = 0; t < TT; t++) {
        const int st = t & 7;
        if (tid < 256 && t + 7 < TT)
            cp_async16(&gbuf[(t + 7) & 7][pr][c4],
                       gproj + ((size_t)(b0 + pr) * TT + t + 7) * 512 + pcol);
        cp_async_commit();

        if (tid < 256) {
            ull a[4], e[4];
#pragma unroll
            for (int r = 0; r < 4; r++) { a[r] = 0ull; e[r] = 0ull; }
            const float* h0p = h_s[p][0];
            const float* h1p = h_s[p][1];
            const float* h2p = h_s[p][2];
            const float* h3p = h_s[p][3];
#pragma unroll
            for (int kp = 0; kp < 64; kp += 2) {
                ulonglong2 u0 = *(const ulonglong2*)(h0p + 2 * kp);
                ulonglong2 u1 = *(const ulonglong2*)(h1p + 2 * kp);
                ulonglong2 u2 = *(const ulonglong2*)(h2p + 2 * kp);
                ulonglong2 u3 = *(const ulonglong2*)(h3p + 2 * kp);
                fma2(a[0], w2[kp], u0.x); fma2(e[0], w2[kp + 1], u0.y);
                fma2(a[1], w2[kp], u1.x); fma2(e[1], w2[kp + 1], u1.y);
                fma2(a[2], w2[kp], u2.x); fma2(e[2], w2[kp + 1], u2.y);
                fma2(a[3], w2[kp], u3.x); fma2(e[3], w2[kp + 1], u3.y);
            }
#pragma unroll
            for (int r = 0; r < 4; r++) {
                float2 f = unpack2(add2(a[r], e[r]));
                z_s[r][tid] = gbuf[st][r][tid] + (f.x + f.y);
            }
        }
        __syncthreads();

        if (tid < 256) {
            float zi = z_s[r2][jj];
            float zf = z_s[r2][64 + jj];
            float zg = z_s[r2][128 + jj];
            float zo = z_s[r2][192 + jj];
            c = fsig(zf) * c + fsig(zi) * fmaxf(zg, 0.f);
            float h = fsig(zo) * fmaxf(c, 0.f);
            float* own = &h_s[p ^ 1][r2][jg];
            *own = h;
            st_remote_f32(own, peer, h);
            if (hseq) hseq[((size_t)(b0 + r2) * TT + t) * 128 + jg] = h;
            __syncwarp();
            if (lane == 0) mbar_arrive_remote(mbar, peer);
        }
        else if (Wout && t > 0) {
            const ull* hp = (const ull*)&h_s[p][orow][0];
            ull oa = 0ull, ob = 0ull;
#pragma unroll
            for (int k2 = 0; k2 < 64; k2 += 2) {
                ulonglong2 hv = *(const ulonglong2*)&hp[k2];
                fma2(oa, wo2[k2][oc], hv.x);
                fma2(ob, wo2[k2 + 1][oc], hv.y);
            }
            float2 f = unpack2(add2(oa, ob));
            outp[((size_t)(b0 + orow) * TT + (t - 1)) * 64 + (int)q * 32 + oc] =
                f.x + f.y + bo_s[oc];
        }

        cp_async_wait6();
        __syncthreads();
        mbar_wait(mbar, par);
        par ^= 1;
        p ^= 1;
    }

    if (Wout && tid >= 256) {
        const ull* hp = (const ull*)&h_s[p][orow][0];
        ull oa = 0ull, ob = 0ull;
#pragma unroll
        for (int k2 = 0; k2 < 64; k2 += 2) {
            ulonglong2 hv = *(const ulonglong2*)&hp[k2];
            fma2(oa, wo2[k2][oc], hv.x);
            fma2(ob, wo2[k2 + 1][oc], hv.y);
        }
        float2 f = unpack2(add2(oa, ob));
        outp[((size_t)(b0 + orow) * TT + (TT - 1)) * 64 + (int)q * 32 + oc] =
            f.x + f.y + bo_s[oc];
    }
}

// ---------------- host orchestration ----------------------------------------
extern "C" void kernel_launch(void* const* d_in, const int* in_sizes, int n_in,
                              void* d_out, int out_size) {
    const float* x    = (const float*)d_in[0];
    const float* Wk1  = (const float*)d_in[1];
    const float* Wr1  = (const float*)d_in[2];
    const float* b1   = (const float*)d_in[3];
    const float* Wk2  = (const float*)d_in[4];
    const float* Wr2  = (const float*)d_in[5];
    const float* b2   = (const float*)d_in[6];
    const float* Wd1k = (const float*)d_in[7];
    const float* Wd1r = (const float*)d_in[8];
    const float* bd1  = (const float*)d_in[9];
    const float* Wd2k = (const float*)d_in[10];
    const float* Wd2r = (const float*)d_in[11];
    const float* bd2  = (const float*)d_in[12];
    const float* Wout = (const float*)d_in[13];
    const float* bout = (const float*)d_in[14];
    float* out = (float*)d_out;

    float *bufG, *h1, *d1, *z;
    cudaGetSymbolAddress((void**)&bufG, g_bufG);
    cudaGetSymbolAddress((void**)&h1,  g_h1);
    cudaGetSymbolAddress((void**)&d1,  g_d1);
    cudaGetSymbolAddress((void**)&z,   g_z);

    const int SMEM_L128 = 57600;
    cudaFuncSetAttribute(lstm128_kernel, cudaFuncAttributeMaxDynamicSharedMemorySize, SMEM_L128);

    dim3 blk(256);

    // 1) G1 = x @ Wk1 + b1                     [BT,512]
    gemm_f32x2_kernel<<<dim3(1024, 4), blk>>>(x, Wk1, b1, bufG, BT, 512, 64);
    // 2) encoder L1 recurrence -> h1           [BT,128]   (256 threads, no fusion)
    lstm128_kernel<<<128, 256, SMEM_L128>>>(bufG, Wr1, h1, nullptr, nullptr, nullptr);
    // 3) G2 = h1 @ Wk2 + b2                    [BT,256]
    gemm_f32x2_kernel<<<dim3(1024, 2), blk>>>(h1, Wk2, b2, bufG, BT, 256, 128);
    // 4) encoder L2 recurrence -> z (last h)   [256,64]   (1 row/CTA, 2 CTA/SM)
    lstm64_kernel<<<256, 128>>>(bufG, Wr2, nullptr, z, nullptr, nullptr, nullptr);
    // 5+6) decoder L1 recurrence with FUSED z@Wd1k+bd1 projection -> d1  [BT,64]
    lstm64_kernel<<<256, 128>>>(nullptr, Wd1r, d1, nullptr, z, Wd1k, bd1);
    // 7) Gd2 = d1 @ Wd2k + bd2                 [BT,512]
    gemm_f32x2_kernel<<<dim3(1024, 4), blk>>>(d1, Wd2k, bd2, bufG, BT, 512, 64);
    // 8) decoder L2 recurrence + FUSED final dense -> out  [BT,64]  (384 threads)
    lstm128_kernel<<<128, 384, SMEM_L128>>>(bufG, Wd2r, nullptr, Wout, bout, out);
}